// round 14
// baseline (speedup 1.0000x reference)
#include <cuda_runtime.h>
#include <cuda_bf16.h>

#define BB      512     // batch
#define DD      256     // feature dim
#define NT2     8       // 512/64 tiles per side
#define NTRI2   36      // NT2*(NT2+1)/2 triangular 64x64 tiles
#define NQ      4       // K split: 4 chunks of 64
#define NGEMM   (NTRI2 * NQ)   // 144 blocks
#define MARGIN  0.2f

__device__ float g_simQ[NQ][BB * BB];   // K-split partial sims (4 MB)
__device__ float g_partials[BB];        // per-anchor-row partial loss
__device__ unsigned int g_done;         // zero-init; reset by finalize

__device__ __forceinline__ float blockReduceSum(float v, float* s_red) {
    #pragma unroll
    for (int o = 16; o > 0; o >>= 1) v += __shfl_down_sync(0xffffffffu, v, o);
    __syncthreads();
    int w = threadIdx.x >> 5, l = threadIdx.x & 31;
    if (l == 0) s_red[w] = v;
    __syncthreads();
    int nw = blockDim.x >> 5;
    if (w == 0) {
        v = (l < nw) ? s_red[l] : 0.0f;
        #pragma unroll
        for (int o = 16; o > 0; o >>= 1) v += __shfl_down_sync(0xffffffffu, v, o);
    }
    return v;  // valid in thread 0
}

// ---------------------------------------------------------------------------
// Kernel 0: symmetric SYRK, 64x64 tiles, 4x4 micro-tiles, K-chunk of 64.
// blockIdx.x = tri*4 + q. 144 blocks ~ 1/SM, single wave.
// ---------------------------------------------------------------------------
__global__ __launch_bounds__(256)
void mcl_gemm_kernel(const float* __restrict__ F) {
    __shared__ __align__(16) float As[64][68];   // [dd][row]
    __shared__ __align__(16) float Bs[64][68];

    const int t  = threadIdx.x;
    const int tx = t & 15, ty = t >> 4;
    const int q  = blockIdx.x & 3;
    int bi = 0, rem = blockIdx.x >> 2;
    while (rem >= NT2 - bi) { rem -= NT2 - bi; bi++; }
    const int bk = bi + rem;
    const int i0 = bi * 64, k0 = bk * 64;
    const int dbase = q * 64;

    const int lc = t & 63;      // d within chunk
    const int lr = t >> 6;      // row group base (rows lr + 4j)

    #pragma unroll
    for (int j = 0; j < 16; j++) {
        As[lc][lr + 4 * j] = F[(size_t)(i0 + lr + 4 * j) * DD + dbase + lc];
        Bs[lc][lr + 4 * j] = F[(size_t)(k0 + lr + 4 * j) * DD + dbase + lc];
    }
    __syncthreads();

    float4 acc0 = {0,0,0,0}, acc1 = {0,0,0,0}, acc2 = {0,0,0,0}, acc3 = {0,0,0,0};
    #pragma unroll 8
    for (int dd = 0; dd < 64; dd++) {
        float4 a = *reinterpret_cast<float4*>(&As[dd][4 * ty]);
        float4 b = *reinterpret_cast<float4*>(&Bs[dd][4 * tx]);
        acc0.x += a.x * b.x; acc0.y += a.x * b.y; acc0.z += a.x * b.z; acc0.w += a.x * b.w;
        acc1.x += a.y * b.x; acc1.y += a.y * b.y; acc1.z += a.y * b.z; acc1.w += a.y * b.w;
        acc2.x += a.z * b.x; acc2.y += a.z * b.y; acc2.z += a.z * b.z; acc2.w += a.z * b.w;
        acc3.x += a.w * b.x; acc3.y += a.w * b.y; acc3.z += a.w * b.z; acc3.w += a.w * b.w;
    }

    float* C = g_simQ[q];
    const int r0 = i0 + 4 * ty, c0 = k0 + 4 * tx;
    *reinterpret_cast<float4*>(&C[(size_t)(r0 + 0) * BB + c0]) = acc0;
    *reinterpret_cast<float4*>(&C[(size_t)(r0 + 1) * BB + c0]) = acc1;
    *reinterpret_cast<float4*>(&C[(size_t)(r0 + 2) * BB + c0]) = acc2;
    *reinterpret_cast<float4*>(&C[(size_t)(r0 + 3) * BB + c0]) = acc3;
    if (bi != bk) {   // mirror (transposed scalar stores)
        C[(size_t)(c0 + 0) * BB + r0] = acc0.x; C[(size_t)(c0 + 0) * BB + r0 + 1] = acc1.x;
        C[(size_t)(c0 + 0) * BB + r0 + 2] = acc2.x; C[(size_t)(c0 + 0) * BB + r0 + 3] = acc3.x;
        C[(size_t)(c0 + 1) * BB + r0] = acc0.y; C[(size_t)(c0 + 1) * BB + r0 + 1] = acc1.y;
        C[(size_t)(c0 + 1) * BB + r0 + 2] = acc2.y; C[(size_t)(c0 + 1) * BB + r0 + 3] = acc3.y;
        C[(size_t)(c0 + 2) * BB + r0] = acc0.z; C[(size_t)(c0 + 2) * BB + r0 + 1] = acc1.z;
        C[(size_t)(c0 + 2) * BB + r0 + 2] = acc2.z; C[(size_t)(c0 + 2) * BB + r0 + 3] = acc3.z;
        C[(size_t)(c0 + 3) * BB + r0] = acc0.w; C[(size_t)(c0 + 3) * BB + r0 + 1] = acc1.w;
        C[(size_t)(c0 + 3) * BB + r0 + 2] = acc2.w; C[(size_t)(c0 + 3) * BB + r0 + 3] = acc3.w;
    }
}

// ---------------------------------------------------------------------------
// Kernel 1: one block per anchor row. Positives compacted (ballot scan) then
// rank-sorted with prefix sums; each negative's hinge sum collapses to
// cnt*c - pref[cnt] via binary search. Fused finalize in last block.
// ---------------------------------------------------------------------------
__global__ __launch_bounds__(256)
void mcl_pair_kernel(const int* __restrict__ labels, float* __restrict__ out) {
    __shared__ int    s_lab[BB];
    __shared__ float  s_pos[BB];       // compacted positives
    __shared__ float  s_sorted[BB];    // sorted positives
    __shared__ float  s_pref[BB + 1];  // prefix sums of sorted positives
    __shared__ int    s_pcnt[32];
    __shared__ int    s_poff[32];
    __shared__ int    s_cnt;
    __shared__ float  s_red[8];
    __shared__ int    s_hist[16];
    __shared__ int    s_isLast;

    const int t    = threadIdx.x;
    const int i    = blockIdx.x;
    const int lane = t & 31;
    const int w    = t >> 5;           // 0..7

    s_lab[t]       = labels[t];
    s_lab[t + 256] = labels[t + 256];
    if (t < 32) s_pcnt[t] = 0;
    if (t == 0) s_pref[0] = 0.0f;      // covers P==0
    __syncthreads();

    const int li = s_lab[i];
    const int kA = t, kB = t + 256;
    float vA = 0.f, vB = 0.f;
    #pragma unroll
    for (int q = 0; q < NQ; q++) {
        vA += g_simQ[q][(size_t)i * BB + kA];
        vB += g_simQ[q][(size_t)i * BB + kB];
    }
    const bool eqA = (s_lab[kA] == li), eqB = (s_lab[kB] == li);
    const bool pA = (kA != i) && eqA, pB = (kB != i) && eqB;
    const unsigned bpA = __ballot_sync(0xffffffffu, pA);
    const unsigned bpB = __ballot_sync(0xffffffffu, pB);
    if (lane == 0) { s_pcnt[w] = __popc(bpA); s_pcnt[8 + w] = __popc(bpB); }
    __syncthreads();
    if (w == 0) {                       // exclusive scan of 16 live pos counts
        int c = s_pcnt[lane], x = c;
        #pragma unroll
        for (int o = 1; o < 32; o <<= 1) {
            int y = __shfl_up_sync(0xffffffffu, x, o);
            if (lane >= o) x += y;
        }
        s_poff[lane] = x - c;
        if (lane == 31) s_cnt = x;
    }
    __syncthreads();
    const unsigned lt = (1u << lane) - 1u;
    if (pA) s_pos[s_poff[w]     + __popc(bpA & lt)] = vA;
    if (pB) s_pos[s_poff[8 + w] + __popc(bpB & lt)] = vB;
    __syncthreads();

    const int P = s_cnt;
    // rank sort + prefix-of-smaller in one pass (thread t handles positive t)
    if (t < P) {
        const float y = s_pos[t];
        int rank = 0; float psum = 0.f;
        for (int qq = 0; qq < P; qq++) {
            float yq = s_pos[qq];
            bool less = (yq < y) || (yq == y && qq < t);
            if (less) { rank++; psum += yq; }
        }
        s_sorted[rank] = y;
        s_pref[rank]   = psum;
        if (rank == P - 1) s_pref[P] = psum + y;   // total (index P)
    }
    __syncthreads();

    // negatives in place: thread's own kA/kB slots
    float acc = 0.f;
    const bool ngA = (kA != i) && !eqA;
    const bool ngB = (kB != i) && !eqB;
    if (ngA & (P > 0)) {
        const float c = MARGIN + vA;
        int lo = 0, hi = P;
        while (lo < hi) { int mid = (lo + hi) >> 1; if (s_sorted[mid] < c) lo = mid + 1; else hi = mid; }
        acc += (float)lo * c - s_pref[lo];
    }
    if (ngB & (P > 0)) {
        const float c = MARGIN + vB;
        int lo = 0, hi = P;
        while (lo < hi) { int mid = (lo + hi) >> 1; if (s_sorted[mid] < c) lo = mid + 1; else hi = mid; }
        acc += (float)lo * c - s_pref[lo];
    }

    float total = blockReduceSum(acc, s_red);
    if (t == 0) {
        g_partials[i] = total;
        __threadfence();
        unsigned v = atomicAdd(&g_done, 1u);
        s_isLast = (v == BB - 1) ? 1 : 0;
    }
    __syncthreads();

    // ---------------- Finalize (last-finishing block) ----------------
    if (s_isLast) {
        __threadfence();
        float part = g_partials[t] + g_partials[t + 256];
        float loss_sum = blockReduceSum(part, s_red);

        if (t < 16) s_hist[t] = 0;
        __syncthreads();
        atomicAdd(&s_hist[s_lab[t]], 1);
        atomicAdd(&s_hist[s_lab[t + 256]], 1);
        __syncthreads();

        if (t == 0) {
            float nv = 0.0f;
            #pragma unroll
            for (int c = 0; c < 16; c++) {
                int hc = s_hist[c];
                if (hc >= 2 && hc < BB) nv += (float)hc;   // posc>0 && negc>0
            }
            int   cl    = s_lab[BB - 1];
            float pcl   = (float)(s_hist[cl] - 1);
            float ncl   = (float)(BB - s_hist[cl]);
            float denom = nv * pcl * ncl;
            out[0] = (denom > 0.0f) ? (loss_sum / denom) : 0.0f;
            g_done = 0;   // reset for next graph replay
        }
    }
}

extern "C" void kernel_launch(void* const* d_in, const int* in_sizes, int n_in,
                              void* d_out, int out_size) {
    const float* F      = (const float*)d_in[0];
    const int*   labels = (const int*)d_in[1];
    float*       out    = (float*)d_out;
    (void)in_sizes; (void)n_in; (void)out_size;

    mcl_gemm_kernel<<<NGEMM, 256>>>(F);
    mcl_pair_kernel<<<BB, 256>>>(labels, out);
}

// round 17
// speedup vs baseline: 1.1555x; 1.1555x over previous
#include <cuda_runtime.h>
#include <cuda_bf16.h>

#define BB      512     // batch
#define DD      256     // feature dim
#define NT2     8       // 512/64 tiles per side
#define NTRI2   36      // NT2*(NT2+1)/2 triangular 64x64 tiles
#define NQ      4       // K split: 4 chunks of 64
#define NGEMM   (NTRI2 * NQ)   // 144 blocks
#define MARGIN  0.2f

__device__ float g_simQ[NQ][BB * BB];   // K-split partial sims (4 MB)
__device__ float g_scale;               // 1/denom (0 if denom<=0), set by gemm blk 0

__device__ __forceinline__ float blockReduceSum(float v, float* s_red) {
    #pragma unroll
    for (int o = 16; o > 0; o >>= 1) v += __shfl_down_sync(0xffffffffu, v, o);
    __syncthreads();
    int w = threadIdx.x >> 5, l = threadIdx.x & 31;
    if (l == 0) s_red[w] = v;
    __syncthreads();
    int nw = blockDim.x >> 5;
    if (w == 0) {
        v = (l < nw) ? s_red[l] : 0.0f;
        #pragma unroll
        for (int o = 16; o > 0; o >>= 1) v += __shfl_down_sync(0xffffffffu, v, o);
    }
    return v;  // valid in thread 0
}

// ---------------------------------------------------------------------------
// Kernel 0: symmetric SYRK, 64x64 tiles, 4x4 micro-tiles, K-chunk of 64.
// Block 0 additionally computes g_scale = 1/denom from labels and zeroes out.
// Fires PDL trigger after stores so the pair kernel can begin its prologue.
// ---------------------------------------------------------------------------
__global__ __launch_bounds__(256)
void mcl_gemm_kernel(const float* __restrict__ F, const int* __restrict__ labels,
                     float* __restrict__ out) {
    __shared__ __align__(16) float As[64][68];   // [dd][row]
    __shared__ __align__(16) float Bs[64][68];
    __shared__ int s_hist[16];

    const int t  = threadIdx.x;
    const int tx = t & 15, ty = t >> 4;
    const int q  = blockIdx.x & 3;
    int bi = 0, rem = blockIdx.x >> 2;
    while (rem >= NT2 - bi) { rem -= NT2 - bi; bi++; }
    const int bk = bi + rem;
    const int i0 = bi * 64, k0 = bk * 64;
    const int dbase = q * 64;

    // Block 0 side-duty: denominator from labels only.
    int  labA = 0, labB = 0, labLast = 0;
    if (blockIdx.x == 0) {
        if (t < 16) s_hist[t] = 0;
        labA = labels[t]; labB = labels[t + 256];
        labLast = labels[BB - 1];
    }

    const int lc = t & 63;      // d within chunk
    const int lr = t >> 6;      // row group base (rows lr + 4j)

    #pragma unroll
    for (int j = 0; j < 16; j++) {
        As[lc][lr + 4 * j] = F[(size_t)(i0 + lr + 4 * j) * DD + dbase + lc];
        Bs[lc][lr + 4 * j] = F[(size_t)(k0 + lr + 4 * j) * DD + dbase + lc];
    }
    __syncthreads();

    if (blockIdx.x == 0) {
        atomicAdd(&s_hist[labA], 1);
        atomicAdd(&s_hist[labB], 1);
    }

    float4 acc0 = {0,0,0,0}, acc1 = {0,0,0,0}, acc2 = {0,0,0,0}, acc3 = {0,0,0,0};
    #pragma unroll 8
    for (int dd = 0; dd < 64; dd++) {
        float4 a = *reinterpret_cast<float4*>(&As[dd][4 * ty]);
        float4 b = *reinterpret_cast<float4*>(&Bs[dd][4 * tx]);
        acc0.x += a.x * b.x; acc0.y += a.x * b.y; acc0.z += a.x * b.z; acc0.w += a.x * b.w;
        acc1.x += a.y * b.x; acc1.y += a.y * b.y; acc1.z += a.y * b.z; acc1.w += a.y * b.w;
        acc2.x += a.z * b.x; acc2.y += a.z * b.y; acc2.z += a.z * b.z; acc2.w += a.z * b.w;
        acc3.x += a.w * b.x; acc3.y += a.w * b.y; acc3.z += a.w * b.z; acc3.w += a.w * b.w;
    }

    float* C = g_simQ[q];
    const int r0 = i0 + 4 * ty, c0 = k0 + 4 * tx;
    *reinterpret_cast<float4*>(&C[(size_t)(r0 + 0) * BB + c0]) = acc0;
    *reinterpret_cast<float4*>(&C[(size_t)(r0 + 1) * BB + c0]) = acc1;
    *reinterpret_cast<float4*>(&C[(size_t)(r0 + 2) * BB + c0]) = acc2;
    *reinterpret_cast<float4*>(&C[(size_t)(r0 + 3) * BB + c0]) = acc3;
    if (bi != bk) {   // mirror (transposed scalar stores)
        C[(size_t)(c0 + 0) * BB + r0] = acc0.x; C[(size_t)(c0 + 0) * BB + r0 + 1] = acc1.x;
        C[(size_t)(c0 + 0) * BB + r0 + 2] = acc2.x; C[(size_t)(c0 + 0) * BB + r0 + 3] = acc3.x;
        C[(size_t)(c0 + 1) * BB + r0] = acc0.y; C[(size_t)(c0 + 1) * BB + r0 + 1] = acc1.y;
        C[(size_t)(c0 + 1) * BB + r0 + 2] = acc2.y; C[(size_t)(c0 + 1) * BB + r0 + 3] = acc3.y;
        C[(size_t)(c0 + 2) * BB + r0] = acc0.z; C[(size_t)(c0 + 2) * BB + r0 + 1] = acc1.z;
        C[(size_t)(c0 + 2) * BB + r0 + 2] = acc2.z; C[(size_t)(c0 + 2) * BB + r0 + 3] = acc3.z;
        C[(size_t)(c0 + 3) * BB + r0] = acc0.w; C[(size_t)(c0 + 3) * BB + r0 + 1] = acc1.w;
        C[(size_t)(c0 + 3) * BB + r0 + 2] = acc2.w; C[(size_t)(c0 + 3) * BB + r0 + 3] = acc3.w;
    }

    if (blockIdx.x == 0) {
        __syncthreads();
        if (t == 0) {
            float nv = 0.0f;
            #pragma unroll
            for (int c = 0; c < 16; c++) {
                int hc = s_hist[c];
                if (hc >= 2 && hc < BB) nv += (float)hc;   // posc>0 && negc>0
            }
            float pcl   = (float)(s_hist[labLast] - 1);
            float ncl   = (float)(BB - s_hist[labLast]);
            float denom = nv * pcl * ncl;
            g_scale = (denom > 0.0f) ? (1.0f / denom) : 0.0f;
            out[0]  = 0.0f;
        }
    }

    // PDL: allow dependent (pair) kernel blocks to launch; full completion of
    // this grid is still what griddepcontrol.wait in the dependent observes.
    asm volatile("griddepcontrol.launch_dependents;");
}

// ---------------------------------------------------------------------------
// Kernel 1: one block per anchor row (PDL-overlapped prologue). Positives
// compacted via ballot scan; negatives in place. Each block atomically
// accumulates total * g_scale into out[0] — no finalize tail.
// ---------------------------------------------------------------------------
__global__ __launch_bounds__(256)
void mcl_pair_kernel(const int* __restrict__ labels, float* __restrict__ out) {
    __shared__ int    s_lab[BB];
    __shared__ float4 s_pos4[132];     // 528 floats, padded positives
    __shared__ int    s_pcnt[32];
    __shared__ int    s_poff[32];
    __shared__ int    s_cnt;
    __shared__ float  s_red[8];

    const int t    = threadIdx.x;
    const int i    = blockIdx.x;
    const int lane = t & 31;
    const int w    = t >> 5;           // 0..7
    float* s_pos = reinterpret_cast<float*>(s_pos4);

    // Prologue — independent of the GEMM's output, overlaps its tail via PDL.
    s_lab[t]       = labels[t];
    s_lab[t + 256] = labels[t + 256];
    if (t < 32) s_pcnt[t] = 0;
    __syncthreads();

    // Wait for the GEMM grid (sim + g_scale + out zeroing) to complete.
    asm volatile("griddepcontrol.wait;");

    const int li = s_lab[i];
    const int kA = t, kB = t + 256;
    float vA = 0.f, vB = 0.f;
    #pragma unroll
    for (int q = 0; q < NQ; q++) {
        vA += g_simQ[q][(size_t)i * BB + kA];
        vB += g_simQ[q][(size_t)i * BB + kB];
    }
    const bool eqA = (s_lab[kA] == li), eqB = (s_lab[kB] == li);
    const bool pA = (kA != i) && eqA, pB = (kB != i) && eqB;
    const unsigned bpA = __ballot_sync(0xffffffffu, pA);
    const unsigned bpB = __ballot_sync(0xffffffffu, pB);
    if (lane == 0) { s_pcnt[w] = __popc(bpA); s_pcnt[8 + w] = __popc(bpB); }
    __syncthreads();
    if (w == 0) {                       // exclusive scan of 16 live pos counts
        int c = s_pcnt[lane], x = c;
        #pragma unroll
        for (int o = 1; o < 32; o <<= 1) {
            int y = __shfl_up_sync(0xffffffffu, x, o);
            if (lane >= o) x += y;
        }
        s_poff[lane] = x - c;
        if (lane == 31) s_cnt = x;
    }
    __syncthreads();
    const unsigned lt = (1u << lane) - 1u;
    if (pA) s_pos[s_poff[w]     + __popc(bpA & lt)] = vA;
    if (pB) s_pos[s_poff[8 + w] + __popc(bpB & lt)] = vB;
    __syncthreads();

    const int P = s_cnt;
    if (t < 4) s_pos[P + t] = 1e30f;    // pad to multiple of 4 (max idx 514 < 528)
    __syncthreads();

    // negatives in place: thread's own kA/kB slots, predicated
    const float t0 = ((kA != i) && !eqA) ? (MARGIN + vA) : -1e30f;
    const float t1 = ((kB != i) && !eqB) ? (MARGIN + vB) : -1e30f;
    float a0 = 0.f, a1 = 0.f;
    const int P4 = (P + 3) >> 2;
    for (int pc = 0; pc < P4; pc++) {
        float4 pv = s_pos4[pc];
        a0 += fmaxf(0.f, t0 - pv.x) + fmaxf(0.f, t0 - pv.y)
            + fmaxf(0.f, t0 - pv.z) + fmaxf(0.f, t0 - pv.w);
        a1 += fmaxf(0.f, t1 - pv.x) + fmaxf(0.f, t1 - pv.y)
            + fmaxf(0.f, t1 - pv.z) + fmaxf(0.f, t1 - pv.w);
    }

    float total = blockReduceSum(a0 + a1, s_red);
    if (t == 0) atomicAdd(out, total * g_scale);   // scaled partial, no tail
}

extern "C" void kernel_launch(void* const* d_in, const int* in_sizes, int n_in,
                              void* d_out, int out_size) {
    const float* F      = (const float*)d_in[0];
    const int*   labels = (const int*)d_in[1];
    float*       out    = (float*)d_out;
    (void)in_sizes; (void)n_in; (void)out_size;

    mcl_gemm_kernel<<<NGEMM, 256>>>(F, labels, out);

    cudaLaunchConfig_t cfg = {};
    cfg.gridDim  = dim3(BB, 1, 1);
    cfg.blockDim = dim3(256, 1, 1);
    cfg.stream   = 0;
    cudaLaunchAttribute attrs[1];
    attrs[0].id = cudaLaunchAttributeProgrammaticStreamSerialization;
    attrs[0].val.programmaticStreamSerializationAllowed = 1;
    cfg.attrs    = attrs;
    cfg.numAttrs = 1;
    cudaLaunchKernelEx(&cfg, mcl_pair_kernel, labels, out);
}